// round 1
// baseline (speedup 1.0000x reference)
#include <cuda_runtime.h>

#define BHN   128          // B*H
#define SEQ   4096
#define DIM   64
#define SPLIT 8
#define ROWS_PER_SPLIT (SEQ / SPLIT)   // 512
#define CHUNK 64
#define EPSF  1e-6f

typedef unsigned long long u64;

// Scratch (device globals: allocation-free per harness rules)
__device__ float g_ctx_partial[BHN * SPLIT * DIM * DIM]; // 16 MB
__device__ float g_cs_partial [BHN * SPLIT * DIM];
__device__ float g_ctx        [BHN * DIM * DIM];         // 2 MB (normalized context)

// ---- packed fp32x2 helpers (Blackwell dual-rate fp32) ----
__device__ __forceinline__ u64 pack_dup(float a) {
    u64 r; asm("mov.b64 %0, {%1, %2};" : "=l"(r) : "f"(a), "f"(a)); return r;
}
__device__ __forceinline__ void fma2(u64 &d, u64 a, u64 b) {
    asm("fma.rn.f32x2 %0, %1, %2, %0;" : "+l"(d) : "l"(a), "l"(b));
}
__device__ __forceinline__ float2 unpack2(u64 a) {
    float2 f; asm("mov.b64 {%0, %1}, %2;" : "=f"(f.x), "=f"(f.y) : "l"(a)); return f;
}

// ============================================================================
// Kernel 1: partial context = (e^K)^T @ V over an n-split, plus partial colsum.
// Block: 256 threads (tx 0..15 -> e tile, ty 0..15 -> d tile). Grid: (SPLIT, BHN).
// ============================================================================
__global__ __launch_bounds__(256, 4)
void ctx_kernel(const float* __restrict__ kp, const float* __restrict__ vp)
{
    __shared__ __align__(16) float s_ek[CHUNK][DIM];   // 16 KB  e^k chunk
    __shared__ __align__(16) float s_v [CHUNK][DIM];   // 16 KB  v chunk
    __shared__ __align__(16) float s_red[16][DIM];     //  4 KB  colsum reduction

    const int tid = threadIdx.x;
    const int tx = tid & 15, ty = tid >> 4;
    const int split = blockIdx.x, bh = blockIdx.y;
    const size_t base = ((size_t)bh * SEQ + (size_t)split * ROWS_PER_SPLIT) * DIM;

    u64 acc[4][2];
#pragma unroll
    for (int i = 0; i < 4; i++) { acc[i][0] = 0ull; acc[i][1] = 0ull; }
    float4 cs = make_float4(0.f, 0.f, 0.f, 0.f);   // colsum for d = 4*tx .. 4*tx+3

    for (int ch = 0; ch < ROWS_PER_SPLIT / CHUNK; ch++) {
        // ---- stage chunk: apply exp to K while loading ----
#pragma unroll
        for (int r = 0; r < 4; r++) {
            const int idx = r * 256 + tid;         // 0..1023 float4s
            const int nl  = idx >> 4;              // 0..63 ; d-group = tx (since 256%16==0)
            const size_t goff = base + (size_t)(ch * CHUNK + nl) * DIM + 4 * tx;
            const float4 kk = *(const float4*)(kp + goff);
            const float e0 = __expf(kk.x), e1 = __expf(kk.y),
                        e2 = __expf(kk.z), e3 = __expf(kk.w);
            *(float4*)&s_ek[nl][4 * tx] = make_float4(e0, e1, e2, e3);
            cs.x += e0; cs.y += e1; cs.z += e2; cs.w += e3;
            *(float4*)&s_v[nl][4 * tx] = *(const float4*)(vp + goff);
        }
        __syncthreads();

        // ---- rank-1 updates: ctx[4ty..][4tx..] += ek[n][d] * v[n][e] ----
#pragma unroll 16
        for (int n = 0; n < CHUNK; n++) {
            const float4 ek = *(const float4*)&s_ek[n][4 * ty];
            const ulonglong2 vv = *(const ulonglong2*)&s_v[n][4 * tx]; // (v0,v1),(v2,v3) packed
            const u64 a0 = pack_dup(ek.x), a1 = pack_dup(ek.y),
                      a2 = pack_dup(ek.z), a3 = pack_dup(ek.w);
            fma2(acc[0][0], a0, vv.x); fma2(acc[0][1], a0, vv.y);
            fma2(acc[1][0], a1, vv.x); fma2(acc[1][1], a1, vv.y);
            fma2(acc[2][0], a2, vv.x); fma2(acc[2][1], a2, vv.y);
            fma2(acc[3][0], a3, vv.x); fma2(acc[3][1], a3, vv.y);
        }
        __syncthreads();
    }

    // ---- colsum partial: reduce over ty for each d ----
    *(float4*)&s_red[ty][4 * tx] = cs;
    __syncthreads();
    const int pbase = bh * SPLIT + split;
    if (tid < DIM) {
        float s = 0.f;
#pragma unroll
        for (int y = 0; y < 16; y++) s += s_red[y][tid];
        g_cs_partial[pbase * DIM + tid] = s;
    }

    // ---- context partial ----
    float* cp = g_ctx_partial + (size_t)pbase * DIM * DIM;
#pragma unroll
    for (int i = 0; i < 4; i++) {
        const float2 lo = unpack2(acc[i][0]);
        const float2 hi = unpack2(acc[i][1]);
        *(float4*)(cp + (size_t)(4 * ty + i) * DIM + 4 * tx) =
            make_float4(lo.x, lo.y, hi.x, hi.y);
    }
}

// ============================================================================
// Kernel 2: reduce split partials and normalize by 1/(colsum*(1+EPS)).
// Grid: BHN blocks, 256 threads.
// ============================================================================
__global__ __launch_bounds__(256)
void reduce_kernel()
{
    const int bh = blockIdx.x, tid = threadIdx.x;
    __shared__ float inv[DIM];
    if (tid < DIM) {
        float s = 0.f;
#pragma unroll
        for (int sp = 0; sp < SPLIT; sp++)
            s += g_cs_partial[(bh * SPLIT + sp) * DIM + tid];
        inv[tid] = 1.0f / (s * (1.0f + EPSF));
    }
    __syncthreads();
#pragma unroll
    for (int r = 0; r < 4; r++) {
        const int i4 = r * 256 + tid;            // float4 index over 1024
        float4 s = make_float4(0.f, 0.f, 0.f, 0.f);
#pragma unroll
        for (int sp = 0; sp < SPLIT; sp++) {
            const float4 p = *(const float4*)(g_ctx_partial +
                (size_t)(bh * SPLIT + sp) * DIM * DIM + 4 * i4);
            s.x += p.x; s.y += p.y; s.z += p.z; s.w += p.w;
        }
        const float iv = inv[i4 >> 4];           // d = (4*i4)/64
        s.x *= iv; s.y *= iv; s.z *= iv; s.w *= iv;
        *(float4*)(g_ctx + (size_t)bh * DIM * DIM + 4 * i4) = s;
    }
}

// ============================================================================
// Kernel 3: out = rowsoftmax(Q) @ ctx. Block handles 64 rows of one (b,h).
// Grid: (SEQ/64, BHN), 256 threads.
// ============================================================================
__global__ __launch_bounds__(256, 4)
void out_kernel(const float* __restrict__ qp, float* __restrict__ outp)
{
    __shared__ __align__(16) float s_p[DIM][68];   // transposed softmax(Q): [d][n], pad 68 for 16B-aligned rows
    __shared__ __align__(16) float s_c[DIM * DIM]; // ctx [d][e]

    const int tid = threadIdx.x;
    const int tx = tid & 15, ty = tid >> 4;
    const int nb = blockIdx.x, bh = blockIdx.y;

    // stage ctx
#pragma unroll
    for (int r = 0; r < 4; r++) {
        const int i4 = r * 256 + tid;
        *(float4*)(s_c + 4 * i4) =
            *(const float4*)(g_ctx + (size_t)bh * DIM * DIM + 4 * i4);
    }

    // row softmax of q: 4 threads per row, 16 elems each, quad-shfl reductions
    {
        const int row = tid >> 2, part = tid & 3;
        const float* qr = qp + ((size_t)bh * SEQ + (size_t)nb * 64 + row) * DIM + part * 16;
        float e[16];
        const float4 a = *(const float4*)(qr +  0);
        const float4 b = *(const float4*)(qr +  4);
        const float4 c = *(const float4*)(qr +  8);
        const float4 d = *(const float4*)(qr + 12);
        e[0]=a.x; e[1]=a.y; e[2]=a.z; e[3]=a.w; e[4]=b.x; e[5]=b.y; e[6]=b.z; e[7]=b.w;
        e[8]=c.x; e[9]=c.y; e[10]=c.z; e[11]=c.w; e[12]=d.x; e[13]=d.y; e[14]=d.z; e[15]=d.w;
        float m = e[0];
#pragma unroll
        for (int i = 1; i < 16; i++) m = fmaxf(m, e[i]);
        m = fmaxf(m, __shfl_xor_sync(0xffffffffu, m, 1));
        m = fmaxf(m, __shfl_xor_sync(0xffffffffu, m, 2));
        float s = 0.f;
#pragma unroll
        for (int i = 0; i < 16; i++) { e[i] = __expf(e[i] - m); s += e[i]; }
        s += __shfl_xor_sync(0xffffffffu, s, 1);
        s += __shfl_xor_sync(0xffffffffu, s, 2);
        const float rinv = 1.0f / s;
#pragma unroll
        for (int i = 0; i < 16; i++) s_p[part * 16 + i][row] = e[i] * rinv;
    }
    __syncthreads();

    // GEMM: out[n][e] = sum_d p[n][d] * ctx[d][e]; rows paired in f32x2 lanes
    u64 acc[2][4];
#pragma unroll
    for (int i = 0; i < 2; i++)
#pragma unroll
        for (int j = 0; j < 4; j++) acc[i][j] = 0ull;

#pragma unroll 16
    for (int d = 0; d < DIM; d++) {
        const ulonglong2 pp = *(const ulonglong2*)&s_p[d][4 * ty]; // (p[n0],p[n1]),(p[n2],p[n3])
        const float4 cv = *(const float4*)(s_c + d * DIM + 4 * tx);
        const u64 c0 = pack_dup(cv.x), c1 = pack_dup(cv.y),
                  c2 = pack_dup(cv.z), c3 = pack_dup(cv.w);
        fma2(acc[0][0], pp.x, c0); fma2(acc[0][1], pp.x, c1);
        fma2(acc[0][2], pp.x, c2); fma2(acc[0][3], pp.x, c3);
        fma2(acc[1][0], pp.y, c0); fma2(acc[1][1], pp.y, c1);
        fma2(acc[1][2], pp.y, c2); fma2(acc[1][3], pp.y, c3);
    }

    // epilogue: acc[i][j] = (out[4ty+2i][e_j], out[4ty+2i+1][e_j])
    const size_t obase = ((size_t)bh * SEQ + (size_t)nb * 64) * DIM;
#pragma unroll
    for (int i = 0; i < 2; i++) {
        const float2 u0 = unpack2(acc[i][0]);
        const float2 u1 = unpack2(acc[i][1]);
        const float2 u2 = unpack2(acc[i][2]);
        const float2 u3 = unpack2(acc[i][3]);
        const int r0 = 4 * ty + 2 * i;
        *(float4*)(outp + obase + (size_t)r0 * DIM + 4 * tx) =
            make_float4(u0.x, u1.x, u2.x, u3.x);
        *(float4*)(outp + obase + (size_t)(r0 + 1) * DIM + 4 * tx) =
            make_float4(u0.y, u1.y, u2.y, u3.y);
    }
}

// ============================================================================
extern "C" void kernel_launch(void* const* d_in, const int* in_sizes, int n_in,
                              void* d_out, int out_size)
{
    const float* q = (const float*)d_in[0];
    const float* k = (const float*)d_in[1];
    const float* v = (const float*)d_in[2];
    float* out = (float*)d_out;

    ctx_kernel  <<<dim3(SPLIT, BHN), 256>>>(k, v);
    reduce_kernel<<<BHN, 256>>>();
    out_kernel  <<<dim3(SEQ / 64, BHN), 256>>>(q, out);
}